// round 14
// baseline (speedup 1.0000x reference)
#include <cuda_runtime.h>

static constexpr int CHW    = 3 * 128 * 128;    // 49152
static constexpr int CHW4   = CHW / 4;          // 12288 float4
static constexpr int S      = 16;
static constexpr int N      = 64;
static constexpr int HALF4  = CHW4 / 2;         // 6144 float4
static constexpr int GRID   = N * S * 2;        // 2048 blocks: (n, s, half)

// Per-(n,s) distance accumulated by exactly 2 blocks via atomicAdd (2-operand
// FP add is commutative -> deterministic). Zero-init; last block resets.
__device__ float        g_dist[N * S];
__device__ unsigned int g_count = 0;

__global__ __launch_bounds__(256)
void fused_min_dist_kernel(const float* __restrict__ inputs,
                           const float* __restrict__ samples,
                           float* __restrict__ out) {
    const int blk = blockIdx.x;          // 0..2047
    const int n   = blk >> 5;
    const int s   = (blk >> 1) & 15;
    const int h   = blk & 1;

    const size_t off = (size_t)h * HALF4;
    const float4* __restrict__ in4 =
        reinterpret_cast<const float4*>(inputs + (size_t)n * CHW) + off;
    const float4* __restrict__ sm4 =
        reinterpret_cast<const float4*>(samples + ((size_t)n * S + s) * CHW) + off;

    // Proven stream shape: 24 iters/thread, 2 plain float4 loads, unroll 4.
    float acc = 0.0f;
    #pragma unroll 4
    for (int i = threadIdx.x; i < HALF4; i += 256) {
        float4 a = in4[i];
        float4 b = sm4[i];
        float dx = b.x - a.x;
        float dy = b.y - a.y;
        float dz = b.z - a.z;
        float dw = b.w - a.w;
        acc = fmaf(dx, dx, acc);
        acc = fmaf(dy, dy, acc);
        acc = fmaf(dz, dz, acc);
        acc = fmaf(dw, dw, acc);
    }

    // Block reduction: warp shuffle then cross-warp via shared.
    __shared__ float sdata[8];
    #pragma unroll
    for (int o = 16; o > 0; o >>= 1)
        acc += __shfl_down_sync(0xffffffffu, acc, o);

    const int lane = threadIdx.x & 31;
    const int wid  = threadIdx.x >> 5;
    if (lane == 0) sdata[wid] = acc;
    __syncthreads();

    __shared__ bool is_last;
    if (wid == 0) {
        acc = (lane < 8) ? sdata[lane] : 0.0f;
        #pragma unroll
        for (int o = 4; o > 0; o >>= 1)
            acc += __shfl_down_sync(0xffffffffu, acc, o);
        if (lane == 0) {
            atomicAdd(&g_dist[n * S + s], acc);   // 2 contributions, commutative
            __threadfence();
            unsigned int prev = atomicInc(&g_count, GRID - 1);  // self-resetting
            is_last = (prev == GRID - 1);
        }
    }
    __syncthreads();

    // ---- last block: min over s, sum over n, write scalar, reset state ----
    if (is_last) {
        __shared__ float sh[N * S];
        // 1. snapshot ALL partials into shared
        for (int p = threadIdx.x; p < N * S; p += 256)
            sh[p] = __ldcg(&g_dist[p]);
        __syncthreads();                 // reads complete before any reset
        // 2. reset accumulators for the next graph replay
        for (int p = threadIdx.x; p < N * S; p += 256)
            g_dist[p] = 0.0f;
        // 3. min over s from the shared snapshot
        __shared__ float mins[N];
        if (threadIdx.x < N) {
            const int nn = threadIdx.x;
            float m = sh[nn * S];
            #pragma unroll
            for (int ss = 1; ss < S; ss++)
                m = fminf(m, sh[nn * S + ss]);
            mins[nn] = m;
        }
        __syncthreads();
        // 4. sum over n (fixed order -> deterministic)
        if (threadIdx.x == 0) {
            float total = 0.0f;
            #pragma unroll
            for (int nn = 0; nn < N; nn++)
                total += mins[nn];
            out[0] = total;
        }
    }
}

extern "C" void kernel_launch(void* const* d_in, const int* in_sizes, int n_in,
                              void* d_out, int out_size) {
    const float* inputs  = (const float*)d_in[0];   // [64,3,128,128]
    const float* samples = (const float*)d_in[1];   // [64,16,3,128,128]
    float* out = (float*)d_out;

    fused_min_dist_kernel<<<GRID, 256>>>(inputs, samples, out);
}